// round 16
// baseline (speedup 1.0000x reference)
#include <cuda_runtime.h>
#include <cuda_fp16.h>
#include <math.h>
#include <stdint.h>

// ---------------------------------------------------------------------------
// RWKV-7 Tmix forward. B=4, T=2048, C=2048, H=32, N=64.
// R16: wkv7 = 512 threads (8 cols/thread), cp.async 4-buffer ring (lookahead
// 3). GEMMs = R13/R15 fp16 1-MMA (proven). Single stream.
// ---------------------------------------------------------------------------

#define BB 4
#define TT 2048
#define CC 2048
#define HH 32
#define NN 64
#define BT (BB*TT)                       // 8192
#define BTC ((size_t)BT*(size_t)CC)      // 16777216

__device__ float g_pool[23ull * 16777216ull];

#define SL_XR 0
#define SL_XW 1
#define SL_XK 2
#define SL_XV 3
#define SL_XA 4
#define SL_XG 5
#define SL_R  6
#define SL_K  7
#define SL_VL 8
#define SL_G  9
#define SL_WD 10
#define SL_A  11
#define SL_S  12
#define SL_Y  19
#define SL_ZS 20
#define SL_SMALL 21
#define SL_WB  22

// ===========================================================================
// helpers
// ===========================================================================
__device__ __forceinline__ uint32_t smem_u32(const void* p) {
    uint32_t a;
    asm("{ .reg .u64 t; cvta.to.shared.u64 t, %1; cvt.u32.u64 %0, t; }"
        : "=r"(a) : "l"(p));
    return a;
}
__device__ __forceinline__ void cpasync16(uint32_t dst, const void* src) {
    asm volatile("cp.async.cg.shared.global [%0], [%1], 16;" :: "r"(dst), "l"(src));
}
__device__ __forceinline__ void ldsm4(uint32_t* r, uint32_t addr) {
    asm volatile("ldmatrix.sync.aligned.m8n8.x4.shared.b16 {%0,%1,%2,%3}, [%4];"
        : "=r"(r[0]), "=r"(r[1]), "=r"(r[2]), "=r"(r[3]) : "r"(addr));
}
__device__ __forceinline__ void mma16816(float* d, const uint32_t* a, const uint32_t* b) {
    asm volatile(
        "mma.sync.aligned.m16n8k16.row.col.f32.f16.f16.f32 "
        "{%0,%1,%2,%3}, {%4,%5,%6,%7}, {%8,%9}, {%0,%1,%2,%3};"
        : "+f"(d[0]), "+f"(d[1]), "+f"(d[2]), "+f"(d[3])
        : "r"(a[0]), "r"(a[1]), "r"(a[2]), "r"(a[3]), "r"(b[0]), "r"(b[1]));
}
__device__ __forceinline__ uint32_t pack_h2(float a, float b) {
    __half2 t = __floats2half2_rn(a, b);
    return *reinterpret_cast<uint32_t*>(&t);
}

// EPI: 0=none, 3=sigmoid(v+bias[n]), 4=decay transform with bias[n]
__device__ __forceinline__ float epi_rt(int epi, float v, float b) {
    if (epi == 3) {
        return 1.f / (1.f + expf(-(v + b)));
    } else if (epi == 4) {
        float z  = v + b;
        float sp = (z < -20.f) ? (-z) : log1pf(expf(-z));
        float w  = -sp - 0.5f;
        return expf(-expf(w));
    }
    return v;
}

// ===========================================================================
// GEMM core: C[M,Ntot] = A_fp16[M,K(lda)] @ B_fp16[Ntot,K]^T, fp32 accum.
// CTA 128x128x32, 2-stage double buffer, warp 64x32 (2x4 warps), 2 CTAs/SM.
// ===========================================================================
#define PADK 40
#define TILE_B (128*PADK*2)              // 10240
#define STG_B  (2*TILE_B)                // 20480
#define HSTAGES 2
#define HSMEM  (HSTAGES*STG_B)           // 40960

template<int EPI_T>
__device__ __forceinline__ void hgemm_body(
    const __half* __restrict__ A, const __half* __restrict__ B,
    float* __restrict__ C, int K, int lda, int Ntot,
    const float* __restrict__ bias, int epi_rt_code, char* sm)
{
    const int tid  = threadIdx.x;
    const int lane = tid & 31;
    const int wid  = tid >> 5;
    const int m0 = blockIdx.y * 128;
    const int n0 = blockIdx.x * 128;
    const int mw = (wid >> 2) * 64;
    const int nw = (wid & 3) * 32;
    const uint32_t sbase = smem_u32(sm);
    const int KT = K >> 5;

    float acc[4][4][4];
#pragma unroll
    for (int mt = 0; mt < 4; mt++)
#pragma unroll
        for (int nt = 0; nt < 4; nt++)
#pragma unroll
            for (int q = 0; q < 4; q++) acc[mt][nt][q] = 0.f;

    auto issue = [&](int kt, int stage) {
        const int k0 = kt << 5;
        const uint32_t sdst = sbase + stage * STG_B;
#pragma unroll
        for (int u = 0; u < 4; u++) {
            int i  = tid + u * 256;
            int op = i >> 9;
            int r  = (i >> 2) & 127;
            int c  = i & 3;
            const __half* src = (op == 0)
                ? A + (size_t)(m0 + r) * lda + k0 + c * 8
                : B + (size_t)(n0 + r) * K   + k0 + c * 8;
            cpasync16(sdst + op * TILE_B + r * (PADK*2) + c * 16, src);
        }
    };

    issue(0, 0);
    asm volatile("cp.async.commit_group;" ::: "memory");

    const int grp = lane >> 3;
    const int l7  = lane & 7;

    for (int kt = 0; kt < KT; kt++) {
        asm volatile("cp.async.wait_group 0;" ::: "memory");
        __syncthreads();

        if (kt + 1 < KT) issue(kt + 1, (kt + 1) & 1);
        asm volatile("cp.async.commit_group;" ::: "memory");

        const int st = kt & 1;
        const uint32_t sA = sbase + st * STG_B;
        const uint32_t sB = sA + TILE_B;

#pragma unroll
        for (int kk = 0; kk < 2; kk++) {
            const int ko = kk * 16;
            uint32_t af[4][4];
#pragma unroll
            for (int mt = 0; mt < 4; mt++) {
                int row = mw + mt * 16 + ((grp & 1) << 3) + l7;
                int kof = ko + ((grp & 2) << 2);
                uint32_t a = row * (PADK*2) + kof * 2;
                ldsm4(af[mt], sA + a);
            }
#pragma unroll
            for (int np = 0; np < 2; np++) {
                int row = nw + np * 16 + ((grp >> 1) << 3) + l7;
                int kof = ko + ((grp & 1) << 3);
                uint32_t a = row * (PADK*2) + kof * 2;
                uint32_t tb[4];
                ldsm4(tb, sB + a);
#pragma unroll
                for (int mt = 0; mt < 4; mt++) mma16816(acc[mt][np*2],   af[mt], tb);
#pragma unroll
                for (int mt = 0; mt < 4; mt++) mma16816(acc[mt][np*2+1], af[mt], tb + 2);
            }
        }
        __syncthreads();
    }

    const int r0 = lane >> 2;
    const int c0 = (lane & 3) * 2;
    const int epi = (EPI_T >= 0) ? EPI_T : epi_rt_code;
#pragma unroll
    for (int mt = 0; mt < 4; mt++) {
#pragma unroll
        for (int nt = 0; nt < 4; nt++) {
            int row = m0 + mw + mt * 16 + r0;
            int col = n0 + nw + nt * 8 + c0;
            float b0 = 0.f, b1 = 0.f;
            if (epi != 0) { b0 = bias[col]; b1 = bias[col + 1]; }
            float v0 = epi_rt(epi, acc[mt][nt][0], b0);
            float v1 = epi_rt(epi, acc[mt][nt][1], b1);
            float v2 = epi_rt(epi, acc[mt][nt][2], b0);
            float v3 = epi_rt(epi, acc[mt][nt][3], b1);
            *(float2*)(C + (size_t)row * Ntot + col)       = make_float2(v0, v1);
            *(float2*)(C + (size_t)(row + 8) * Ntot + col) = make_float2(v2, v3);
        }
    }
}

template<int EPI>
__global__ void __launch_bounds__(256, 2)
hgemm(const __half* __restrict__ A, const __half* __restrict__ B,
      float* __restrict__ C, int K, int lda, int Ntot, const float* __restrict__ bias)
{
    extern __shared__ char sm[];
    hgemm_body<EPI>(A, B, C, K, lda, Ntot, bias, EPI, sm);
}

__global__ void __launch_bounds__(256, 2)
hgemm_batch3(const __half* A0, float* C0, const __half* A1, float* C1,
             const __half* A2, float* C2,
             const __half* B0, const __half* B1, const __half* B2)
{
    extern __shared__ char sm[];
    const __half *A, *B; float* C;
    if (blockIdx.z == 0)      { A=A0; B=B0; C=C0; }
    else if (blockIdx.z == 1) { A=A1; B=B1; C=C1; }
    else                      { A=A2; B=B2; C=C2; }
    hgemm_body<0>(A, B, C, CC, CC, CC, nullptr, 0, sm);
}

#define HCATN 320
__global__ void __launch_bounds__(256, 2)
hgemm_s2(const __half* hcat,
         const __half* B0, const __half* B1, const __half* B2, const __half* B3,
         float* C0, float* C1, float* C2, float* C3,
         const float* bias0, const float* bias1, const float* bias2)
{
    extern __shared__ char sm[];
    int K, epi, aoff;
    const __half* B; float* C; const float* bias;
    if (blockIdx.z == 0)      { K=64;  epi=4; aoff=0;   B=B0; C=C0; bias=bias0; }
    else if (blockIdx.z == 1) { K=64;  epi=3; aoff=64;  B=B1; C=C1; bias=bias1; }
    else if (blockIdx.z == 2) { K=32;  epi=3; aoff=256; B=B2; C=C2; bias=bias2; }
    else                      { K=128; epi=0; aoff=128; B=B3; C=C3; bias=nullptr; }
    hgemm_body<-1>(hcat + aoff, B, C, K, HCATN, CC, bias, epi, sm);
}

// ===========================================================================
// Stage-1 fused LoRA GEMM: 5 column segments of W1cat[320][2048].
// ===========================================================================
#define S1_ATILE (128*PADK*2)
#define S1_BTILE (64*PADK*2)
#define S1_STG   (S1_ATILE + S1_BTILE)
#define S1_SMEM  (3*S1_STG)

__global__ void __launch_bounds__(256, 2)
hgemm_s1(const __half* __restrict__ xw, const __half* __restrict__ xa,
         const __half* __restrict__ xg, const __half* __restrict__ xv,
         const __half* __restrict__ W1, __half* __restrict__ H)
{
    extern __shared__ char sm[];
    const int tid  = threadIdx.x;
    const int lane = tid & 31;
    const int wid  = tid >> 5;
    const int seg  = blockIdx.x;
    const int m0   = blockIdx.y * 128;
    const int n0w  = seg * 64;
    const uint32_t sbase = smem_u32(sm);

    const __half* A;
    if (seg == 0)      A = xw;
    else if (seg == 1) A = xa;
    else if (seg <= 3) A = xg;
    else               A = xv;

    const int mw = (wid >> 1) * 32;
    const int nw = (wid & 1) * 32;

    float acc[2][4][4];
#pragma unroll
    for (int mt = 0; mt < 2; mt++)
#pragma unroll
        for (int nt = 0; nt < 4; nt++)
#pragma unroll
            for (int q = 0; q < 4; q++) acc[mt][nt][q] = 0.f;

    auto issue = [&](int kt, int stage) {
        const int k0 = kt << 5;
        const uint32_t sdst = sbase + stage * S1_STG;
#pragma unroll
        for (int u = 0; u < 3; u++) {
            int i = tid + u * 256;
            if (i < 512) {
                int r = i >> 2, c = i & 3;
                const __half* src = A + (size_t)(m0 + r) * CC + k0 + c * 8;
                cpasync16(sdst + r * (PADK*2) + c * 16, src);
            } else {
                int j = i - 512;
                int r = j >> 2, c = j & 3;
                const __half* src = W1 + (size_t)(n0w + r) * CC + k0 + c * 8;
                cpasync16(sdst + S1_ATILE + r * (PADK*2) + c * 16, src);
            }
        }
    };

#pragma unroll
    for (int s = 0; s < 2; s++) {
        issue(s, s);
        asm volatile("cp.async.commit_group;" ::: "memory");
    }

    const int grp = lane >> 3;
    const int l7  = lane & 7;
    const int KT = CC >> 5;

    for (int kt = 0; kt < KT; kt++) {
        asm volatile("cp.async.wait_group 1;" ::: "memory");
        __syncthreads();

        const int st = kt % 3;
        const uint32_t sA = sbase + st * S1_STG;
        const uint32_t sB = sA + S1_ATILE;

#pragma unroll
        for (int kk = 0; kk < 2; kk++) {
            const int ko = kk * 16;
            uint32_t af[2][4];
#pragma unroll
            for (int mt = 0; mt < 2; mt++) {
                int row = mw + mt * 16 + ((grp & 1) << 3) + l7;
                int kof = ko + ((grp & 2) << 2);
                uint32_t a = row * (PADK*2) + kof * 2;
                ldsm4(af[mt], sA + a);
            }
#pragma unroll
            for (int np = 0; np < 2; np++) {
                int row = nw + np * 16 + ((grp >> 1) << 3) + l7;
                int kof = ko + ((grp & 1) << 3);
                uint32_t a = row * (PADK*2) + kof * 2;
                uint32_t tb[4];
                ldsm4(tb, sB + a);
#pragma unroll
                for (int mt = 0; mt < 2; mt++) mma16816(acc[mt][np*2],   af[mt], tb);
#pragma unroll
                for (int mt = 0; mt < 2; mt++) mma16816(acc[mt][np*2+1], af[mt], tb + 2);
            }
        }

        int nkt = kt + 2;
        if (nkt < KT) issue(nkt, nkt % 3);
        asm volatile("cp.async.commit_group;" ::: "memory");
    }

    const int r0 = lane >> 2;
    const int c0 = (lane & 3) * 2;
#pragma unroll
    for (int mt = 0; mt < 2; mt++) {
#pragma unroll
        for (int nt = 0; nt < 4; nt++) {
            float v[4];
#pragma unroll
            for (int q = 0; q < 4; q++) {
                float t = acc[mt][nt][q];
                if (seg == 0)              t = tanhf(t);
                else if (seg == 2 || seg == 3) t = 1.f / (1.f + expf(-t));
                v[q] = t;
            }
            int row = m0 + mw + mt * 16 + r0;
            int col = seg * 64 + nw + nt * 8 + c0;
            *(uint32_t*)&H[(size_t)row * HCATN + col]     = pack_h2(v[0], v[1]);
            *(uint32_t*)&H[(size_t)(row+8) * HCATN + col] = pack_h2(v[2], v[3]);
        }
    }
}

// ===========================================================================
// Weight transpose: W[K][N] fp32 -> T[N][K] fp16
// ===========================================================================
__device__ __forceinline__ void transpose_body(const float* __restrict__ W,
                                               __half* __restrict__ T,
                                               int K, int N)
{
    __shared__ float tile[32][33];
    int bx = blockIdx.x * 32;
    int by = blockIdx.y * 32;
#pragma unroll
    for (int j = 0; j < 32; j += 8)
        tile[threadIdx.y + j][threadIdx.x] =
            W[(size_t)(by + threadIdx.y + j) * N + bx + threadIdx.x];
    __syncthreads();
#pragma unroll
    for (int j = 0; j < 32; j += 8) {
        float v = tile[threadIdx.x][threadIdx.y + j];
        int n = bx + threadIdx.y + j;
        int k = by + threadIdx.x;
        T[(size_t)n * K + k] = __float2half(v);
    }
}

__global__ void transpose_split(const float* __restrict__ W,
                                __half* __restrict__ T, int K, int N)
{
    transpose_body(W, T, K, N);
}

__global__ void transpose_big4(const float* W0, const float* W1_, const float* W2_, const float* W3_,
                               __half* t0, __half* t1, __half* t2, __half* t3)
{
    const float* W; __half* T;
    if (blockIdx.z == 0)      { W = W0;  T = t0; }
    else if (blockIdx.z == 1) { W = W1_; T = t1; }
    else if (blockIdx.z == 2) { W = W2_; T = t2; }
    else                      { W = W3_; T = t3; }
    transpose_body(W, T, CC, CC);
}

// ---------------------------------------------------------------------------
// Token-shift mixing, single fp16 output per stream.
// ---------------------------------------------------------------------------
__global__ void mix_split_kernel(const float* __restrict__ x,
    const float* __restrict__ mr, const float* __restrict__ mw,
    const float* __restrict__ mk, const float* __restrict__ mv,
    const float* __restrict__ ma, const float* __restrict__ mg,
    __half* __restrict__ xr, __half* __restrict__ xw,
    __half* __restrict__ xk, __half* __restrict__ xv,
    __half* __restrict__ xa, __half* __restrict__ xg)
{
    size_t i = (size_t)blockIdx.x * blockDim.x + threadIdx.x;
    size_t n4 = BTC / 4;
    if (i >= n4) return;
    size_t e = i * 4;
    int c  = (int)(e % CC);
    int bt = (int)(e / CC);
    int t  = bt % TT;

    float4 xc = ((const float4*)x)[i];
    float4 xp = make_float4(0.f, 0.f, 0.f, 0.f);
    if (t > 0) xp = ((const float4*)x)[i - CC/4];
    float4 xx = make_float4(xp.x-xc.x, xp.y-xc.y, xp.z-xc.z, xp.w-xc.w);

    int c4 = c / 4;
#define DOMIX(MV, OUT) { \
        float4 m = ((const float4*)MV)[c4]; \
        float4 o = make_float4(xc.x + xx.x*m.x, xc.y + xx.y*m.y, \
                               xc.z + xx.z*m.z, xc.w + xx.w*m.w); \
        ((uint2*)OUT)[i] = make_uint2(pack_h2(o.x, o.y), pack_h2(o.z, o.w)); }
    DOMIX(mr, xr); DOMIX(mw, xw); DOMIX(mk, xk);
    DOMIX(mv, xv); DOMIX(ma, xa); DOMIX(mg, xg);
#undef DOMIX
}

// ---------------------------------------------------------------------------
__device__ __forceinline__ float warp_sum(float v) {
#pragma unroll
    for (int o = 16; o > 0; o >>= 1) v += __shfl_xor_sync(0xffffffffu, v, o);
    return v;
}

// ---------------------------------------------------------------------------
// WKV7 recurrence. cp.async 4-buffer ring (lookahead 3); 512 threads/block,
// thread (row=tid>>3, cg=tid&7) owns S[row][cg*8..+7]. One block per (b,h).
// ---------------------------------------------------------------------------
#define WSTG 448      // floats per stage: 7 arrays x 64

__global__ void __launch_bounds__(512)
wkv7_kernel(const float* __restrict__ r_,  const float* __restrict__ wd_,
            const float* __restrict__ k_,  const float* __restrict__ a_,
            const float* __restrict__ vl_, const float* __restrict__ s_,
            const float* __restrict__ v0_,
            const float* __restrict__ misc_kkk, const float* __restrict__ misc_a,
            float* __restrict__ yT)
{
    __shared__ __align__(16) float sb[4 * WSTG];
    const int bh  = blockIdx.x;
    const int b   = bh >> 5, h = bh & 31;
    const int tid = threadIdx.x;
    const int row = tid >> 3;            // 0..63
    const int cg  = tid & 7;             // 0..7
    const int cb  = cg * 8;
    const size_t src0  = ((size_t)b * TT) * CC + (size_t)h * NN;
    const size_t ybase = (size_t)bh * TT * NN;
    const uint32_t sbb = smem_u32(sb);

    // producers: threads 0..111, one 16B chunk each
    const float* gsrc = nullptr;
    uint32_t soff = 0;
    if (tid < 112) {
        int arr = tid >> 4, ch = tid & 15;
        const float* p;
        if (arr == 0)      p = r_;
        else if (arr == 1) p = wd_;
        else if (arr == 2) p = k_;
        else if (arr == 3) p = a_;
        else if (arr == 4) p = vl_;
        else if (arr == 5) p = s_;
        else               p = v0_;
        gsrc = p + src0 + ch * 4;
        soff = (uint32_t)(arr * 64 + ch * 4) * 4u;
    }

    float mkk[8], mah[8];
#pragma unroll
    for (int j = 0; j < 8; j++) {
        mkk[j] = misc_kkk[h * NN + cb + j];
        mah[j] = misc_a[h * NN + cb + j];
    }

    float st[8];
#pragma unroll
    for (int j = 0; j < 8; j++) st[j] = 0.f;

    auto issue = [&](int t, int stage) {
        if (t < TT && tid < 112)
            cpasync16(sbb + (uint32_t)stage * (WSTG * 4u) + soff,
                      gsrc + (size_t)t * CC);
        asm volatile("cp.async.commit_group;" ::: "memory");
    };

    issue(0, 0);
    issue(1, 1);
    issue(2, 2);

    for (int t = 0; t < TT; t++) {
        asm volatile("cp.async.wait_group 2;" ::: "memory");
        __syncthreads();

        issue(t + 3, (t + 3) & 3);

        const float* base = sb + (t & 3) * WSTG;

        // raw k, a for this thread's 8 columns
        float kraw[8], av[8];
        {
            const float4* k4p = (const float4*)(base + 2 * 64 + cb);
            const float4* a4p = (const float4*)(base + 3 * 64 + cb);
#pragma unroll
            for (int q = 0; q < 2; q++) {
                float4 kq = k4p[q], aq = a4p[q];
                kraw[q*4+0] = kq.x; kraw[q*4+1] = kq.y;
                kraw[q*4+2] = kq.z; kraw[q*4+3] = kq.w;
                av[q*4+0] = aq.x; av[q*4+1] = aq.y;
                av[q*4+2] = aq.z; av[q*4+3] = aq.w;
            }
        }

        float ssq = 0.f, spos = 0.f;
#pragma unroll
        for (int j = 0; j < 8; j++) {
            float kkj = kraw[j] * mkk[j];
            ssq  = fmaf(kkj, kkj, ssq);
            spos = fmaf(st[j], kkj, spos);
        }
        ssq  += __shfl_xor_sync(0xffffffffu, ssq, 1);
        ssq  += __shfl_xor_sync(0xffffffffu, ssq, 2);
        ssq  += __shfl_xor_sync(0xffffffffu, ssq, 4);
        spos += __shfl_xor_sync(0xffffffffu, spos, 1);
        spos += __shfl_xor_sync(0xffffffffu, spos, 2);
        spos += __shfl_xor_sync(0xffffffffu, spos, 4);
        float invn = 1.f / fmaxf(sqrtf(ssq), 1e-12f);
        float sai  = -spos * invn * invn;   // aa = -kk; norm^2 folded

        float vlr = base[4 * 64 + row];
        float sr  = base[5 * 64 + row];
        float v0r = base[6 * 64 + row];
        float vi  = vlr + (v0r - vlr) * sr;

        const float4* r4p = (const float4*)(base + 0 * 64 + cb);
        const float4* w4p = (const float4*)(base + 1 * 64 + cb);
        float y = 0.f;
#pragma unroll
        for (int q = 0; q < 2; q++) {
            float4 wq = w4p[q], rq = r4p[q];
            float wa[4] = {wq.x, wq.y, wq.z, wq.w};
            float ra[4] = {rq.x, rq.y, rq.z, rq.w};
#pragma unroll
            for (int jj = 0; jj < 4; jj++) {
                int j = q * 4 + jj;
                float kkj = kraw[j] * mkk[j];
                float bb  = kkj * av[j];
                float fk  = kraw[j] * fmaf(av[j] - 1.f, mah[j], 1.f);
                float ns  = fmaf(sai, bb, fmaf(vi, fk, st[j] * wa[jj]));
                st[j] = ns;
                y = fmaf(ns, ra[jj], y);
            }
        }
        y += __shfl_xor_sync(0xffffffffu, y, 1);
        y += __shfl_xor_sync(0xffffffffu, y, 2);
        y += __shfl_xor_sync(0xffffffffu, y, 4);
        if (cg == 0) yT[ybase + (size_t)t * NN + row] = y;
    }
}

// ---------------------------------------------------------------------------
// GroupNorm + bonus + gate -> z fp16
// ---------------------------------------------------------------------------
__global__ void post_kernel(const float* __restrict__ yT,
                            const float* __restrict__ r_, const float* __restrict__ k_,
                            const float* __restrict__ a_, const float* __restrict__ vl_,
                            const float* __restrict__ s_, const float* __restrict__ v0_,
                            const float* __restrict__ g,  const float* __restrict__ faaaa,
                            const float* __restrict__ misc_a,
                            const float* __restrict__ lnw, const float* __restrict__ lnb,
                            __half* __restrict__ z)
{
    int gw   = (blockIdx.x * blockDim.x + threadIdx.x) >> 5;
    int lane = threadIdx.x & 31;
    if (gw >= BT * HH) return;
    int h  = gw % HH;
    int bt = gw / HH;
    int b  = bt / TT, t = bt % TT;

    size_t src = (size_t)bt * CC + (size_t)h * NN;
    size_t dst = (((size_t)(b*HH + h)) * TT + t) * NN;
    int n0 = lane, n1 = lane + 32;
    int c0 = h*NN + n0, c1 = h*NN + n1;

    float y0 = yT[dst+n0], y1 = yT[dst+n1];
    float sum = warp_sum(y0 + y1);
    float sq  = warp_sum(y0*y0 + y1*y1);
    float mu  = sum * (1.f/64.f);
    float var = sq * (1.f/64.f) - mu*mu;
    float rs  = rsqrtf(var + 6.4e-4f);

    float k0 = k_[src+n0], k1 = k_[src+n1];
    float a0 = a_[src+n0], a1 = a_[src+n1];
    float fk0 = k0 * fmaf(a0 - 1.f, misc_a[c0], 1.f);
    float fk1 = k1 * fmaf(a1 - 1.f, misc_a[c1], 1.f);
    float rk = r_[src+n0]*fk0*faaaa[c0] + r_[src+n1]*fk1*faaaa[c1];
    float srk = warp_sum(rk);

    float vv0 = vl_[src+n0], vv1 = vl_[src+n1];
    float fv0 = vv0 + (v0_[src+n0] - vv0) * s_[src+n0];
    float fv1 = vv1 + (v0_[src+n1] - vv1) * s_[src+n1];

    float z0 = ((y0 - mu)*rs*lnw[c0] + lnb[c0] + srk*fv0) * g[src+n0];
    float z1 = ((y1 - mu)*rs*lnw[c1] + lnb[c1] + srk*fv1) * g[src+n1];
    z[src+n0] = __float2half(z0);
    z[src+n1] = __float2half(z1);
}

__global__ void copy4_kernel(const float* __restrict__ src, float* __restrict__ dst,
                             size_t n4)
{
    size_t i = (size_t)blockIdx.x * blockDim.x + threadIdx.x;
    if (i < n4) ((float4*)dst)[i] = ((const float4*)src)[i];
}

// ---------------------------------------------------------------------------
// launch (single stream)
// ---------------------------------------------------------------------------
extern "C" void kernel_launch(void* const* d_in, const int* in_sizes, int n_in,
                              void* d_out, int out_size)
{
    const float* x         = (const float*)d_in[0];
    const float* v0        = (const float*)d_in[1];
    const float* maa_r     = (const float*)d_in[2];
    const float* maa_w     = (const float*)d_in[3];
    const float* maa_k     = (const float*)d_in[4];
    const float* maa_v     = (const float*)d_in[5];
    const float* maa_a     = (const float*)d_in[6];
    const float* maa_g     = (const float*)d_in[7];
    const float* time_decay= (const float*)d_in[8];
    const float* faaaa     = (const float*)d_in[9];
    const float* time_aaaaa= (const float*)d_in[10];
    const float* td_w1     = (const float*)d_in[11];
    const float* td_w2     = (const float*)d_in[12];
    const float* aaa_w1    = (const float*)d_in[13];
    const float* aaa_w2    = (const float*)d_in[14];
    const float* gate_w1   = (const float*)d_in[15];
    const float* gate_w2   = (const float*)d_in[16];
    const float* mv_w1     = (const float*)d_in[17];
    const float* mv_w2     = (const float*)d_in[18];
    const float* misc_v    = (const float*)d_in[19];
    const float* misc_kkk  = (const float*)d_in[20];
    const float* misc_a    = (const float*)d_in[21];
    const float* Wr        = (const float*)d_in[22];
    const float* Wk        = (const float*)d_in[23];
    const float* Wv        = (const float*)d_in[24];
    const float* Wo        = (const float*)d_in[25];
    const float* ln_w      = (const float*)d_in[26];
    const float* ln_b      = (const float*)d_in[27];

    float* pool = nullptr;
    cudaGetSymbolAddress((void**)&pool, g_pool);

    __half* xr = (__half*)(pool + (size_t)SL_XR * BTC);
    __half* xw = (__half*)(pool + (size_t)SL_XW * BTC);
    __half* xk = (__half*)(pool + (size_t)SL_XK * BTC);
    __half* xv = (__half*)(pool + (size_t)SL_XV * BTC);
    __half* xa = (__half*)(pool + (size_t)SL_XA * BTC);
    __half* xg = (__half*)(pool + (size_t)SL_XG * BTC);

    float* r_ = pool + (size_t)SL_R  * BTC;
    float* k_ = pool + (size_t)SL_K  * BTC;
    float* vl = pool + (size_t)SL_VL * BTC;
    float* g_ = pool + (size_t)SL_G  * BTC;
    float* wd = pool + (size_t)SL_WD * BTC;
    float* a_ = pool + (size_t)SL_A  * BTC;
    float* s_ = pool + (size_t)SL_S  * BTC;
    float* yT = pool + (size_t)SL_Y  * BTC;
    __half* z_ = (__half*)(pool + (size_t)SL_ZS * BTC);

    __half* sb16 = (__half*)(pool + (size_t)SL_SMALL * BTC);
    __half* hcat  = sb16;
    __half* W1    = hcat + (size_t)BT * HCATN;
    __half* tdw   = W1   + (size_t)HCATN * CC;
    __half* aaaw  = tdw  + (size_t)CC * 64;
    __half* gatew = aaaw + (size_t)CC * 64;
    __half* mvw   = gatew+ (size_t)CC * 128;

    __half* wb = (__half*)(pool + (size_t)SL_WB * BTC);
    const size_t WSZ = (size_t)CC * CC;
    __half* WrT = wb;
    __half* WkT = wb + WSZ;
    __half* WvT = wb + 2*WSZ;
    __half* WoT = wb + 3*WSZ;

    cudaFuncSetAttribute(hgemm<0>, cudaFuncAttributeMaxDynamicSharedMemorySize, HSMEM);
    cudaFuncSetAttribute(hgemm_batch3, cudaFuncAttributeMaxDynamicSharedMemorySize, HSMEM);
    cudaFuncSetAttribute(hgemm_s2, cudaFuncAttributeMaxDynamicSharedMemorySize, HSMEM);
    cudaFuncSetAttribute(hgemm_s1, cudaFuncAttributeMaxDynamicSharedMemorySize, S1_SMEM);

    dim3 tb(32, 8);
    size_t n4 = BTC / 4;

    // k0: merged big weight transposes
    transpose_big4<<<dim3(CC/32, CC/32, 4), tb>>>(
        Wr, Wk, Wv, Wo, WrT, WkT, WvT, WoT);

    // k1: token-shift mixing -> fp16
    mix_split_kernel<<<(unsigned)((n4 + 255) / 256), 256>>>(
        x, maa_r, maa_w, maa_k, maa_v, maa_a, maa_g,
        xr, xw, xk, xv, xa, xg);

    // k2: v0 passthrough
    if ((size_t)out_size >= 2 * BTC) {
        copy4_kernel<<<(unsigned)((n4 + 255) / 256), 256>>>(
            v0, (float*)d_out + BTC, n4);
    } else {
        copy4_kernel<<<1, 256>>>(v0, pool + (size_t)SL_R * BTC, 0);
    }

    // k3: merged big projections r/k/v
    hgemm_batch3<<<dim3(CC/128, BT/128, 3), 256, HSMEM>>>(
        xr, r_,  xk, k_,  xv, vl, WrT, WkT, WvT);

    // small weight transposes
    transpose_split<<<dim3(64/32,  CC/32), tb>>>(td_w1,   W1,                 CC, 64);
    transpose_split<<<dim3(64/32,  CC/32), tb>>>(aaa_w1,  W1 + (size_t)64*CC, CC, 64);
    transpose_split<<<dim3(128/32, CC/32), tb>>>(gate_w1, W1 + (size_t)128*CC,CC, 128);
    transpose_split<<<dim3(32/32,  CC/32), tb>>>(mv_w1,   W1 + (size_t)256*CC,CC, 32);
    transpose_split<<<dim3(CC/32, 64/32),  tb>>>(td_w2,  tdw,  64,  CC);
    transpose_split<<<dim3(CC/32, 64/32),  tb>>>(aaa_w2, aaaw, 64,  CC);
    transpose_split<<<dim3(CC/32, 128/32), tb>>>(gate_w2,gatew,128, CC);
    transpose_split<<<dim3(CC/32, 32/32),  tb>>>(mv_w2,  mvw,  32,  CC);

    // stage-1 fused LoRA GEMM
    hgemm_s1<<<dim3(5, BT/128), 256, S1_SMEM>>>(
        xw, xa, xg, xv, W1, hcat);

    // merged stage-2 (td, aaa, mv, gate)
    hgemm_s2<<<dim3(CC/128, BT/128, 4), 256, HSMEM>>>(
        hcat, tdw, aaaw, mvw, gatew,
        wd, a_, s_, g_, time_decay, time_aaaaa, misc_v);

    // WKV7 recurrence (cp.async ring, 512 threads)
    wkv7_kernel<<<BB*HH, 512>>>(r_, wd, k_, a_, vl, s_, v0, misc_kkk, misc_a, yT);

    // groupnorm + bonus + gate -> z fp16
    post_kernel<<<(BT*HH)/8, 256>>>(yT, r_, k_, a_, vl, s_, v0, g_, faaaa,
                                    misc_a, ln_w, ln_b, z_);

    // output projection directly into d_out
    hgemm<0><<<dim3(CC/128, BT/128), 256, HSMEM>>>(
        z_, WoT, (float*)d_out, CC, CC, CC, nullptr);
}

// round 17
// speedup vs baseline: 1.0441x; 1.0441x over previous
#include <cuda_runtime.h>
#include <cuda_fp16.h>
#include <math.h>
#include <stdint.h>

// ---------------------------------------------------------------------------
// RWKV-7 Tmix forward. B=4, T=2048, C=2048, H=32, N=64.
// R17: wkv7 = R15's 256-thread layout + 4-buffer ring (lookahead 3) + tree
// reductions on the serial chain. GEMMs = R13/R15 fp16 1-MMA (proven).
// ---------------------------------------------------------------------------

#define BB 4
#define TT 2048
#define CC 2048
#define HH 32
#define NN 64
#define BT (BB*TT)                       // 8192
#define BTC ((size_t)BT*(size_t)CC)      // 16777216

__device__ float g_pool[23ull * 16777216ull];

#define SL_XR 0
#define SL_XW 1
#define SL_XK 2
#define SL_XV 3
#define SL_XA 4
#define SL_XG 5
#define SL_R  6
#define SL_K  7
#define SL_VL 8
#define SL_G  9
#define SL_WD 10
#define SL_A  11
#define SL_S  12
#define SL_Y  19
#define SL_ZS 20
#define SL_SMALL 21
#define SL_WB  22

// ===========================================================================
// helpers
// ===========================================================================
__device__ __forceinline__ uint32_t smem_u32(const void* p) {
    uint32_t a;
    asm("{ .reg .u64 t; cvta.to.shared.u64 t, %1; cvt.u32.u64 %0, t; }"
        : "=r"(a) : "l"(p));
    return a;
}
__device__ __forceinline__ void cpasync16(uint32_t dst, const void* src) {
    asm volatile("cp.async.cg.shared.global [%0], [%1], 16;" :: "r"(dst), "l"(src));
}
__device__ __forceinline__ void ldsm4(uint32_t* r, uint32_t addr) {
    asm volatile("ldmatrix.sync.aligned.m8n8.x4.shared.b16 {%0,%1,%2,%3}, [%4];"
        : "=r"(r[0]), "=r"(r[1]), "=r"(r[2]), "=r"(r[3]) : "r"(addr));
}
__device__ __forceinline__ void mma16816(float* d, const uint32_t* a, const uint32_t* b) {
    asm volatile(
        "mma.sync.aligned.m16n8k16.row.col.f32.f16.f16.f32 "
        "{%0,%1,%2,%3}, {%4,%5,%6,%7}, {%8,%9}, {%0,%1,%2,%3};"
        : "+f"(d[0]), "+f"(d[1]), "+f"(d[2]), "+f"(d[3])
        : "r"(a[0]), "r"(a[1]), "r"(a[2]), "r"(a[3]), "r"(b[0]), "r"(b[1]));
}
__device__ __forceinline__ uint32_t pack_h2(float a, float b) {
    __half2 t = __floats2half2_rn(a, b);
    return *reinterpret_cast<uint32_t*>(&t);
}

// EPI: 0=none, 3=sigmoid(v+bias[n]), 4=decay transform with bias[n]
__device__ __forceinline__ float epi_rt(int epi, float v, float b) {
    if (epi == 3) {
        return 1.f / (1.f + expf(-(v + b)));
    } else if (epi == 4) {
        float z  = v + b;
        float sp = (z < -20.f) ? (-z) : log1pf(expf(-z));
        float w  = -sp - 0.5f;
        return expf(-expf(w));
    }
    return v;
}

// ===========================================================================
// GEMM core: C[M,Ntot] = A_fp16[M,K(lda)] @ B_fp16[Ntot,K]^T, fp32 accum.
// CTA 128x128x32, 2-stage double buffer, warp 64x32 (2x4 warps), 2 CTAs/SM.
// ===========================================================================
#define PADK 40
#define TILE_B (128*PADK*2)              // 10240
#define STG_B  (2*TILE_B)                // 20480
#define HSTAGES 2
#define HSMEM  (HSTAGES*STG_B)           // 40960

template<int EPI_T>
__device__ __forceinline__ void hgemm_body(
    const __half* __restrict__ A, const __half* __restrict__ B,
    float* __restrict__ C, int K, int lda, int Ntot,
    const float* __restrict__ bias, int epi_rt_code, char* sm)
{
    const int tid  = threadIdx.x;
    const int lane = tid & 31;
    const int wid  = tid >> 5;
    const int m0 = blockIdx.y * 128;
    const int n0 = blockIdx.x * 128;
    const int mw = (wid >> 2) * 64;
    const int nw = (wid & 3) * 32;
    const uint32_t sbase = smem_u32(sm);
    const int KT = K >> 5;

    float acc[4][4][4];
#pragma unroll
    for (int mt = 0; mt < 4; mt++)
#pragma unroll
        for (int nt = 0; nt < 4; nt++)
#pragma unroll
            for (int q = 0; q < 4; q++) acc[mt][nt][q] = 0.f;

    auto issue = [&](int kt, int stage) {
        const int k0 = kt << 5;
        const uint32_t sdst = sbase + stage * STG_B;
#pragma unroll
        for (int u = 0; u < 4; u++) {
            int i  = tid + u * 256;
            int op = i >> 9;
            int r  = (i >> 2) & 127;
            int c  = i & 3;
            const __half* src = (op == 0)
                ? A + (size_t)(m0 + r) * lda + k0 + c * 8
                : B + (size_t)(n0 + r) * K   + k0 + c * 8;
            cpasync16(sdst + op * TILE_B + r * (PADK*2) + c * 16, src);
        }
    };

    issue(0, 0);
    asm volatile("cp.async.commit_group;" ::: "memory");

    const int grp = lane >> 3;
    const int l7  = lane & 7;

    for (int kt = 0; kt < KT; kt++) {
        asm volatile("cp.async.wait_group 0;" ::: "memory");
        __syncthreads();

        if (kt + 1 < KT) issue(kt + 1, (kt + 1) & 1);
        asm volatile("cp.async.commit_group;" ::: "memory");

        const int st = kt & 1;
        const uint32_t sA = sbase + st * STG_B;
        const uint32_t sB = sA + TILE_B;

#pragma unroll
        for (int kk = 0; kk < 2; kk++) {
            const int ko = kk * 16;
            uint32_t af[4][4];
#pragma unroll
            for (int mt = 0; mt < 4; mt++) {
                int row = mw + mt * 16 + ((grp & 1) << 3) + l7;
                int kof = ko + ((grp & 2) << 2);
                uint32_t a = row * (PADK*2) + kof * 2;
                ldsm4(af[mt], sA + a);
            }
#pragma unroll
            for (int np = 0; np < 2; np++) {
                int row = nw + np * 16 + ((grp >> 1) << 3) + l7;
                int kof = ko + ((grp & 1) << 3);
                uint32_t a = row * (PADK*2) + kof * 2;
                uint32_t tb[4];
                ldsm4(tb, sB + a);
#pragma unroll
                for (int mt = 0; mt < 4; mt++) mma16816(acc[mt][np*2],   af[mt], tb);
#pragma unroll
                for (int mt = 0; mt < 4; mt++) mma16816(acc[mt][np*2+1], af[mt], tb + 2);
            }
        }
        __syncthreads();
    }

    const int r0 = lane >> 2;
    const int c0 = (lane & 3) * 2;
    const int epi = (EPI_T >= 0) ? EPI_T : epi_rt_code;
#pragma unroll
    for (int mt = 0; mt < 4; mt++) {
#pragma unroll
        for (int nt = 0; nt < 4; nt++) {
            int row = m0 + mw + mt * 16 + r0;
            int col = n0 + nw + nt * 8 + c0;
            float b0 = 0.f, b1 = 0.f;
            if (epi != 0) { b0 = bias[col]; b1 = bias[col + 1]; }
            float v0 = epi_rt(epi, acc[mt][nt][0], b0);
            float v1 = epi_rt(epi, acc[mt][nt][1], b1);
            float v2 = epi_rt(epi, acc[mt][nt][2], b0);
            float v3 = epi_rt(epi, acc[mt][nt][3], b1);
            *(float2*)(C + (size_t)row * Ntot + col)       = make_float2(v0, v1);
            *(float2*)(C + (size_t)(row + 8) * Ntot + col) = make_float2(v2, v3);
        }
    }
}

template<int EPI>
__global__ void __launch_bounds__(256, 2)
hgemm(const __half* __restrict__ A, const __half* __restrict__ B,
      float* __restrict__ C, int K, int lda, int Ntot, const float* __restrict__ bias)
{
    extern __shared__ char sm[];
    hgemm_body<EPI>(A, B, C, K, lda, Ntot, bias, EPI, sm);
}

__global__ void __launch_bounds__(256, 2)
hgemm_batch3(const __half* A0, float* C0, const __half* A1, float* C1,
             const __half* A2, float* C2,
             const __half* B0, const __half* B1, const __half* B2)
{
    extern __shared__ char sm[];
    const __half *A, *B; float* C;
    if (blockIdx.z == 0)      { A=A0; B=B0; C=C0; }
    else if (blockIdx.z == 1) { A=A1; B=B1; C=C1; }
    else                      { A=A2; B=B2; C=C2; }
    hgemm_body<0>(A, B, C, CC, CC, CC, nullptr, 0, sm);
}

#define HCATN 320
__global__ void __launch_bounds__(256, 2)
hgemm_s2(const __half* hcat,
         const __half* B0, const __half* B1, const __half* B2, const __half* B3,
         float* C0, float* C1, float* C2, float* C3,
         const float* bias0, const float* bias1, const float* bias2)
{
    extern __shared__ char sm[];
    int K, epi, aoff;
    const __half* B; float* C; const float* bias;
    if (blockIdx.z == 0)      { K=64;  epi=4; aoff=0;   B=B0; C=C0; bias=bias0; }
    else if (blockIdx.z == 1) { K=64;  epi=3; aoff=64;  B=B1; C=C1; bias=bias1; }
    else if (blockIdx.z == 2) { K=32;  epi=3; aoff=256; B=B2; C=C2; bias=bias2; }
    else                      { K=128; epi=0; aoff=128; B=B3; C=C3; bias=nullptr; }
    hgemm_body<-1>(hcat + aoff, B, C, K, HCATN, CC, bias, epi, sm);
}

// ===========================================================================
// Stage-1 fused LoRA GEMM: 5 column segments of W1cat[320][2048].
// ===========================================================================
#define S1_ATILE (128*PADK*2)
#define S1_BTILE (64*PADK*2)
#define S1_STG   (S1_ATILE + S1_BTILE)
#define S1_SMEM  (3*S1_STG)

__global__ void __launch_bounds__(256, 2)
hgemm_s1(const __half* __restrict__ xw, const __half* __restrict__ xa,
         const __half* __restrict__ xg, const __half* __restrict__ xv,
         const __half* __restrict__ W1, __half* __restrict__ H)
{
    extern __shared__ char sm[];
    const int tid  = threadIdx.x;
    const int lane = tid & 31;
    const int wid  = tid >> 5;
    const int seg  = blockIdx.x;
    const int m0   = blockIdx.y * 128;
    const int n0w  = seg * 64;
    const uint32_t sbase = smem_u32(sm);

    const __half* A;
    if (seg == 0)      A = xw;
    else if (seg == 1) A = xa;
    else if (seg <= 3) A = xg;
    else               A = xv;

    const int mw = (wid >> 1) * 32;
    const int nw = (wid & 1) * 32;

    float acc[2][4][4];
#pragma unroll
    for (int mt = 0; mt < 2; mt++)
#pragma unroll
        for (int nt = 0; nt < 4; nt++)
#pragma unroll
            for (int q = 0; q < 4; q++) acc[mt][nt][q] = 0.f;

    auto issue = [&](int kt, int stage) {
        const int k0 = kt << 5;
        const uint32_t sdst = sbase + stage * S1_STG;
#pragma unroll
        for (int u = 0; u < 3; u++) {
            int i = tid + u * 256;
            if (i < 512) {
                int r = i >> 2, c = i & 3;
                const __half* src = A + (size_t)(m0 + r) * CC + k0 + c * 8;
                cpasync16(sdst + r * (PADK*2) + c * 16, src);
            } else {
                int j = i - 512;
                int r = j >> 2, c = j & 3;
                const __half* src = W1 + (size_t)(n0w + r) * CC + k0 + c * 8;
                cpasync16(sdst + S1_ATILE + r * (PADK*2) + c * 16, src);
            }
        }
    };

#pragma unroll
    for (int s = 0; s < 2; s++) {
        issue(s, s);
        asm volatile("cp.async.commit_group;" ::: "memory");
    }

    const int grp = lane >> 3;
    const int l7  = lane & 7;
    const int KT = CC >> 5;

    for (int kt = 0; kt < KT; kt++) {
        asm volatile("cp.async.wait_group 1;" ::: "memory");
        __syncthreads();

        const int st = kt % 3;
        const uint32_t sA = sbase + st * S1_STG;
        const uint32_t sB = sA + S1_ATILE;

#pragma unroll
        for (int kk = 0; kk < 2; kk++) {
            const int ko = kk * 16;
            uint32_t af[2][4];
#pragma unroll
            for (int mt = 0; mt < 2; mt++) {
                int row = mw + mt * 16 + ((grp & 1) << 3) + l7;
                int kof = ko + ((grp & 2) << 2);
                uint32_t a = row * (PADK*2) + kof * 2;
                ldsm4(af[mt], sA + a);
            }
#pragma unroll
            for (int np = 0; np < 2; np++) {
                int row = nw + np * 16 + ((grp >> 1) << 3) + l7;
                int kof = ko + ((grp & 1) << 3);
                uint32_t a = row * (PADK*2) + kof * 2;
                uint32_t tb[4];
                ldsm4(tb, sB + a);
#pragma unroll
                for (int mt = 0; mt < 2; mt++) mma16816(acc[mt][np*2],   af[mt], tb);
#pragma unroll
                for (int mt = 0; mt < 2; mt++) mma16816(acc[mt][np*2+1], af[mt], tb + 2);
            }
        }

        int nkt = kt + 2;
        if (nkt < KT) issue(nkt, nkt % 3);
        asm volatile("cp.async.commit_group;" ::: "memory");
    }

    const int r0 = lane >> 2;
    const int c0 = (lane & 3) * 2;
#pragma unroll
    for (int mt = 0; mt < 2; mt++) {
#pragma unroll
        for (int nt = 0; nt < 4; nt++) {
            float v[4];
#pragma unroll
            for (int q = 0; q < 4; q++) {
                float t = acc[mt][nt][q];
                if (seg == 0)              t = tanhf(t);
                else if (seg == 2 || seg == 3) t = 1.f / (1.f + expf(-t));
                v[q] = t;
            }
            int row = m0 + mw + mt * 16 + r0;
            int col = seg * 64 + nw + nt * 8 + c0;
            *(uint32_t*)&H[(size_t)row * HCATN + col]     = pack_h2(v[0], v[1]);
            *(uint32_t*)&H[(size_t)(row+8) * HCATN + col] = pack_h2(v[2], v[3]);
        }
    }
}

// ===========================================================================
// Weight transpose: W[K][N] fp32 -> T[N][K] fp16
// ===========================================================================
__device__ __forceinline__ void transpose_body(const float* __restrict__ W,
                                               __half* __restrict__ T,
                                               int K, int N)
{
    __shared__ float tile[32][33];
    int bx = blockIdx.x * 32;
    int by = blockIdx.y * 32;
#pragma unroll
    for (int j = 0; j < 32; j += 8)
        tile[threadIdx.y + j][threadIdx.x] =
            W[(size_t)(by + threadIdx.y + j) * N + bx + threadIdx.x];
    __syncthreads();
#pragma unroll
    for (int j = 0; j < 32; j += 8) {
        float v = tile[threadIdx.x][threadIdx.y + j];
        int n = bx + threadIdx.y + j;
        int k = by + threadIdx.x;
        T[(size_t)n * K + k] = __float2half(v);
    }
}

__global__ void transpose_split(const float* __restrict__ W,
                                __half* __restrict__ T, int K, int N)
{
    transpose_body(W, T, K, N);
}

__global__ void transpose_big4(const float* W0, const float* W1_, const float* W2_, const float* W3_,
                               __half* t0, __half* t1, __half* t2, __half* t3)
{
    const float* W; __half* T;
    if (blockIdx.z == 0)      { W = W0;  T = t0; }
    else if (blockIdx.z == 1) { W = W1_; T = t1; }
    else if (blockIdx.z == 2) { W = W2_; T = t2; }
    else                      { W = W3_; T = t3; }
    transpose_body(W, T, CC, CC);
}

// ---------------------------------------------------------------------------
// Token-shift mixing, single fp16 output per stream.
// ---------------------------------------------------------------------------
__global__ void mix_split_kernel(const float* __restrict__ x,
    const float* __restrict__ mr, const float* __restrict__ mw,
    const float* __restrict__ mk, const float* __restrict__ mv,
    const float* __restrict__ ma, const float* __restrict__ mg,
    __half* __restrict__ xr, __half* __restrict__ xw,
    __half* __restrict__ xk, __half* __restrict__ xv,
    __half* __restrict__ xa, __half* __restrict__ xg)
{
    size_t i = (size_t)blockIdx.x * blockDim.x + threadIdx.x;
    size_t n4 = BTC / 4;
    if (i >= n4) return;
    size_t e = i * 4;
    int c  = (int)(e % CC);
    int bt = (int)(e / CC);
    int t  = bt % TT;

    float4 xc = ((const float4*)x)[i];
    float4 xp = make_float4(0.f, 0.f, 0.f, 0.f);
    if (t > 0) xp = ((const float4*)x)[i - CC/4];
    float4 xx = make_float4(xp.x-xc.x, xp.y-xc.y, xp.z-xc.z, xp.w-xc.w);

    int c4 = c / 4;
#define DOMIX(MV, OUT) { \
        float4 m = ((const float4*)MV)[c4]; \
        float4 o = make_float4(xc.x + xx.x*m.x, xc.y + xx.y*m.y, \
                               xc.z + xx.z*m.z, xc.w + xx.w*m.w); \
        ((uint2*)OUT)[i] = make_uint2(pack_h2(o.x, o.y), pack_h2(o.z, o.w)); }
    DOMIX(mr, xr); DOMIX(mw, xw); DOMIX(mk, xk);
    DOMIX(mv, xv); DOMIX(ma, xa); DOMIX(mg, xg);
#undef DOMIX
}

// ---------------------------------------------------------------------------
__device__ __forceinline__ float warp_sum(float v) {
#pragma unroll
    for (int o = 16; o > 0; o >>= 1) v += __shfl_xor_sync(0xffffffffu, v, o);
    return v;
}

// ---------------------------------------------------------------------------
// WKV7 recurrence. cp.async 4-buffer ring (lookahead 3); 256 threads/block,
// thread (row=tid>>2, cg=tid&3) owns S[row][cg*16..+15]. One block per (b,h).
// Tree-reductions on the serial chain.
// ---------------------------------------------------------------------------
#define WSTG 448      // floats per stage: 7 arrays x 64

__global__ void __launch_bounds__(256)
wkv7_kernel(const float* __restrict__ r_,  const float* __restrict__ wd_,
            const float* __restrict__ k_,  const float* __restrict__ a_,
            const float* __restrict__ vl_, const float* __restrict__ s_,
            const float* __restrict__ v0_,
            const float* __restrict__ misc_kkk, const float* __restrict__ misc_a,
            float* __restrict__ yT)
{
    __shared__ __align__(16) float sb[4 * WSTG];
    const int bh  = blockIdx.x;
    const int b   = bh >> 5, h = bh & 31;
    const int tid = threadIdx.x;
    const int row = tid >> 2;
    const int cg  = tid & 3;
    const int cb  = cg * 16;
    const size_t src0  = ((size_t)b * TT) * CC + (size_t)h * NN;
    const size_t ybase = (size_t)bh * TT * NN;
    const uint32_t sbb = smem_u32(sb);

    // producers: threads 0..111, one 16B chunk each (arr = tid/16, chunk = tid%16)
    const float* gsrc = nullptr;
    uint32_t soff = 0;
    if (tid < 112) {
        int arr = tid >> 4, ch = tid & 15;
        const float* p;
        if (arr == 0)      p = r_;
        else if (arr == 1) p = wd_;
        else if (arr == 2) p = k_;
        else if (arr == 3) p = a_;
        else if (arr == 4) p = vl_;
        else if (arr == 5) p = s_;
        else               p = v0_;
        gsrc = p + src0 + ch * 4;
        soff = (uint32_t)(arr * 64 + ch * 4) * 4u;
    }

    float mkk[16], mah[16];
#pragma unroll
    for (int j = 0; j < 16; j++) {
        mkk[j] = misc_kkk[h * NN + cb + j];
        mah[j] = misc_a[h * NN + cb + j];
    }

    float st[16];
#pragma unroll
    for (int j = 0; j < 16; j++) st[j] = 0.f;

    auto issue = [&](int t, int stage) {
        if (t < TT && tid < 112)
            cpasync16(sbb + (uint32_t)stage * (WSTG * 4u) + soff,
                      gsrc + (size_t)t * CC);
        asm volatile("cp.async.commit_group;" ::: "memory");
    };

    issue(0, 0);
    issue(1, 1);
    issue(2, 2);

    for (int t = 0; t < TT; t++) {
        asm volatile("cp.async.wait_group 2;" ::: "memory");
        __syncthreads();

        issue(t + 3, (t + 3) & 3);

        const float* base = sb + (t & 3) * WSTG;

        // raw k, a for this thread's 16 columns
        float kraw[16], av[16];
        {
            const float4* k4p = (const float4*)(base + 2 * 64 + cb);
            const float4* a4p = (const float4*)(base + 3 * 64 + cb);
#pragma unroll
            for (int q = 0; q < 4; q++) {
                float4 kq = k4p[q], aq = a4p[q];
                kraw[q*4+0] = kq.x; kraw[q*4+1] = kq.y;
                kraw[q*4+2] = kq.z; kraw[q*4+3] = kq.w;
                av[q*4+0] = aq.x; av[q*4+1] = aq.y;
                av[q*4+2] = aq.z; av[q*4+3] = aq.w;
            }
        }

        // kk values and tree-reduced ssq / spos (shortens serial dep chain)
        float kk[16];
        float sq8[8], sp8[8];
#pragma unroll
        for (int j = 0; j < 8; j++) {
            float k0 = kraw[2*j]   * mkk[2*j];
            float k1 = kraw[2*j+1] * mkk[2*j+1];
            kk[2*j] = k0; kk[2*j+1] = k1;
            sq8[j] = fmaf(k0, k0, k1 * k1);
            sp8[j] = fmaf(st[2*j], k0, st[2*j+1] * k1);
        }
        float sq4[4], sp4[4];
#pragma unroll
        for (int j = 0; j < 4; j++) {
            sq4[j] = sq8[2*j] + sq8[2*j+1];
            sp4[j] = sp8[2*j] + sp8[2*j+1];
        }
        float ssq  = (sq4[0] + sq4[1]) + (sq4[2] + sq4[3]);
        float spos = (sp4[0] + sp4[1]) + (sp4[2] + sp4[3]);
        ssq  += __shfl_xor_sync(0xffffffffu, ssq, 1);
        ssq  += __shfl_xor_sync(0xffffffffu, ssq, 2);
        spos += __shfl_xor_sync(0xffffffffu, spos, 1);
        spos += __shfl_xor_sync(0xffffffffu, spos, 2);
        float invn = 1.f / fmaxf(sqrtf(ssq), 1e-12f);
        float sai  = -spos * invn * invn;   // aa = -kk; norm^2 folded

        // value-residual mix for this row
        float vlr = base[4 * 64 + row];
        float sr  = base[5 * 64 + row];
        float v0r = base[6 * 64 + row];
        float vi  = vlr + (v0r - vlr) * sr;

        // state update + y (tree-reduced y)
        const float4* r4p = (const float4*)(base + 0 * 64 + cb);
        const float4* w4p = (const float4*)(base + 1 * 64 + cb);
        float y4[4];
#pragma unroll
        for (int q = 0; q < 4; q++) {
            float4 wq = w4p[q], rq = r4p[q];
            float wa[4] = {wq.x, wq.y, wq.z, wq.w};
            float ra[4] = {rq.x, rq.y, rq.z, rq.w};
            float yq0 = 0.f, yq1 = 0.f;
#pragma unroll
            for (int jj = 0; jj < 4; jj++) {
                int j = q * 4 + jj;
                float bb  = kk[j] * av[j];
                float fk  = kraw[j] * fmaf(av[j] - 1.f, mah[j], 1.f);
                float ns  = fmaf(sai, bb, fmaf(vi, fk, st[j] * wa[jj]));
                st[j] = ns;
                if (jj & 1) yq1 = fmaf(ns, ra[jj], yq1);
                else        yq0 = fmaf(ns, ra[jj], yq0);
            }
            y4[q] = yq0 + yq1;
        }
        float y = (y4[0] + y4[1]) + (y4[2] + y4[3]);
        y += __shfl_xor_sync(0xffffffffu, y, 1);
        y += __shfl_xor_sync(0xffffffffu, y, 2);
        if (cg == 0) yT[ybase + (size_t)t * NN + row] = y;
    }
}

// ---------------------------------------------------------------------------
// GroupNorm + bonus + gate -> z fp16
// ---------------------------------------------------------------------------
__global__ void post_kernel(const float* __restrict__ yT,
                            const float* __restrict__ r_, const float* __restrict__ k_,
                            const float* __restrict__ a_, const float* __restrict__ vl_,
                            const float* __restrict__ s_, const float* __restrict__ v0_,
                            const float* __restrict__ g,  const float* __restrict__ faaaa,
                            const float* __restrict__ misc_a,
                            const float* __restrict__ lnw, const float* __restrict__ lnb,
                            __half* __restrict__ z)
{
    int gw   = (blockIdx.x * blockDim.x + threadIdx.x) >> 5;
    int lane = threadIdx.x & 31;
    if (gw >= BT * HH) return;
    int h  = gw % HH;
    int bt = gw / HH;
    int b  = bt / TT, t = bt % TT;

    size_t src = (size_t)bt * CC + (size_t)h * NN;
    size_t dst = (((size_t)(b*HH + h)) * TT + t) * NN;
    int n0 = lane, n1 = lane + 32;
    int c0 = h*NN + n0, c1 = h*NN + n1;

    float y0 = yT[dst+n0], y1 = yT[dst+n1];
    float sum = warp_sum(y0 + y1);
    float sq  = warp_sum(y0*y0 + y1*y1);
    float mu  = sum * (1.f/64.f);
    float var = sq * (1.f/64.f) - mu*mu;
    float rs  = rsqrtf(var + 6.4e-4f);

    float k0 = k_[src+n0], k1 = k_[src+n1];
    float a0 = a_[src+n0], a1 = a_[src+n1];
    float fk0 = k0 * fmaf(a0 - 1.f, misc_a[c0], 1.f);
    float fk1 = k1 * fmaf(a1 - 1.f, misc_a[c1], 1.f);
    float rk = r_[src+n0]*fk0*faaaa[c0] + r_[src+n1]*fk1*faaaa[c1];
    float srk = warp_sum(rk);

    float vv0 = vl_[src+n0], vv1 = vl_[src+n1];
    float fv0 = vv0 + (v0_[src+n0] - vv0) * s_[src+n0];
    float fv1 = vv1 + (v0_[src+n1] - vv1) * s_[src+n1];

    float z0 = ((y0 - mu)*rs*lnw[c0] + lnb[c0] + srk*fv0) * g[src+n0];
    float z1 = ((y1 - mu)*rs*lnw[c1] + lnb[c1] + srk*fv1) * g[src+n1];
    z[src+n0] = __float2half(z0);
    z[src+n1] = __float2half(z1);
}

__global__ void copy4_kernel(const float* __restrict__ src, float* __restrict__ dst,
                             size_t n4)
{
    size_t i = (size_t)blockIdx.x * blockDim.x + threadIdx.x;
    if (i < n4) ((float4*)dst)[i] = ((const float4*)src)[i];
}

// ---------------------------------------------------------------------------
// launch (single stream)
// ---------------------------------------------------------------------------
extern "C" void kernel_launch(void* const* d_in, const int* in_sizes, int n_in,
                              void* d_out, int out_size)
{
    const float* x         = (const float*)d_in[0];
    const float* v0        = (const float*)d_in[1];
    const float* maa_r     = (const float*)d_in[2];
    const float* maa_w     = (const float*)d_in[3];
    const float* maa_k     = (const float*)d_in[4];
    const float* maa_v     = (const float*)d_in[5];
    const float* maa_a     = (const float*)d_in[6];
    const float* maa_g     = (const float*)d_in[7];
    const float* time_decay= (const float*)d_in[8];
    const float* faaaa     = (const float*)d_in[9];
    const float* time_aaaaa= (const float*)d_in[10];
    const float* td_w1     = (const float*)d_in[11];
    const float* td_w2     = (const float*)d_in[12];
    const float* aaa_w1    = (const float*)d_in[13];
    const float* aaa_w2    = (const float*)d_in[14];
    const float* gate_w1   = (const float*)d_in[15];
    const float* gate_w2   = (const float*)d_in[16];
    const float* mv_w1     = (const float*)d_in[17];
    const float* mv_w2     = (const float*)d_in[18];
    const float* misc_v    = (const float*)d_in[19];
    const float* misc_kkk  = (const float*)d_in[20];
    const float* misc_a    = (const float*)d_in[21];
    const float* Wr        = (const float*)d_in[22];
    const float* Wk        = (const float*)d_in[23];
    const float* Wv        = (const float*)d_in[24];
    const float* Wo        = (const float*)d_in[25];
    const float* ln_w      = (const float*)d_in[26];
    const float* ln_b      = (const float*)d_in[27];

    float* pool = nullptr;
    cudaGetSymbolAddress((void**)&pool, g_pool);

    __half* xr = (__half*)(pool + (size_t)SL_XR * BTC);
    __half* xw = (__half*)(pool + (size_t)SL_XW * BTC);
    __half* xk = (__half*)(pool + (size_t)SL_XK * BTC);
    __half* xv = (__half*)(pool + (size_t)SL_XV * BTC);
    __half* xa = (__half*)(pool + (size_t)SL_XA * BTC);
    __half* xg = (__half*)(pool + (size_t)SL_XG * BTC);

    float* r_ = pool + (size_t)SL_R  * BTC;
    float* k_ = pool + (size_t)SL_K  * BTC;
    float* vl = pool + (size_t)SL_VL * BTC;
    float* g_ = pool + (size_t)SL_G  * BTC;
    float* wd = pool + (size_t)SL_WD * BTC;
    float* a_ = pool + (size_t)SL_A  * BTC;
    float* s_ = pool + (size_t)SL_S  * BTC;
    float* yT = pool + (size_t)SL_Y  * BTC;
    __half* z_ = (__half*)(pool + (size_t)SL_ZS * BTC);

    __half* sb16 = (__half*)(pool + (size_t)SL_SMALL * BTC);
    __half* hcat  = sb16;
    __half* W1    = hcat + (size_t)BT * HCATN;
    __half* tdw   = W1   + (size_t)HCATN * CC;
    __half* aaaw  = tdw  + (size_t)CC * 64;
    __half* gatew = aaaw + (size_t)CC * 64;
    __half* mvw   = gatew+ (size_t)CC * 128;

    __half* wb = (__half*)(pool + (size_t)SL_WB * BTC);
    const size_t WSZ = (size_t)CC * CC;
    __half* WrT = wb;
    __half* WkT = wb + WSZ;
    __half* WvT = wb + 2*WSZ;
    __half* WoT = wb + 3*WSZ;

    cudaFuncSetAttribute(hgemm<0>, cudaFuncAttributeMaxDynamicSharedMemorySize, HSMEM);
    cudaFuncSetAttribute(hgemm_batch3, cudaFuncAttributeMaxDynamicSharedMemorySize, HSMEM);
    cudaFuncSetAttribute(hgemm_s2, cudaFuncAttributeMaxDynamicSharedMemorySize, HSMEM);
    cudaFuncSetAttribute(hgemm_s1, cudaFuncAttributeMaxDynamicSharedMemorySize, S1_SMEM);

    dim3 tb(32, 8);
    size_t n4 = BTC / 4;

    // k0: merged big weight transposes
    transpose_big4<<<dim3(CC/32, CC/32, 4), tb>>>(
        Wr, Wk, Wv, Wo, WrT, WkT, WvT, WoT);

    // k1: token-shift mixing -> fp16
    mix_split_kernel<<<(unsigned)((n4 + 255) / 256), 256>>>(
        x, maa_r, maa_w, maa_k, maa_v, maa_a, maa_g,
        xr, xw, xk, xv, xa, xg);

    // k2: v0 passthrough
    if ((size_t)out_size >= 2 * BTC) {
        copy4_kernel<<<(unsigned)((n4 + 255) / 256), 256>>>(
            v0, (float*)d_out + BTC, n4);
    } else {
        copy4_kernel<<<1, 256>>>(v0, pool + (size_t)SL_R * BTC, 0);
    }

    // k3: merged big projections r/k/v
    hgemm_batch3<<<dim3(CC/128, BT/128, 3), 256, HSMEM>>>(
        xr, r_,  xk, k_,  xv, vl, WrT, WkT, WvT);

    // small weight transposes
    transpose_split<<<dim3(64/32,  CC/32), tb>>>(td_w1,   W1,                 CC, 64);
    transpose_split<<<dim3(64/32,  CC/32), tb>>>(aaa_w1,  W1 + (size_t)64*CC, CC, 64);
    transpose_split<<<dim3(128/32, CC/32), tb>>>(gate_w1, W1 + (size_t)128*CC,CC, 128);
    transpose_split<<<dim3(32/32,  CC/32), tb>>>(mv_w1,   W1 + (size_t)256*CC,CC, 32);
    transpose_split<<<dim3(CC/32, 64/32),  tb>>>(td_w2,  tdw,  64,  CC);
    transpose_split<<<dim3(CC/32, 64/32),  tb>>>(aaa_w2, aaaw, 64,  CC);
    transpose_split<<<dim3(CC/32, 128/32), tb>>>(gate_w2,gatew,128, CC);
    transpose_split<<<dim3(CC/32, 32/32),  tb>>>(mv_w2,  mvw,  32,  CC);

    // stage-1 fused LoRA GEMM
    hgemm_s1<<<dim3(5, BT/128), 256, S1_SMEM>>>(
        xw, xa, xg, xv, W1, hcat);

    // merged stage-2 (td, aaa, mv, gate)
    hgemm_s2<<<dim3(CC/128, BT/128, 4), 256, HSMEM>>>(
        hcat, tdw, aaaw, mvw, gatew,
        wd, a_, s_, g_, time_decay, time_aaaaa, misc_v);

    // WKV7 recurrence (cp.async 4-buffer ring, 256 threads)
    wkv7_kernel<<<BB*HH, 256>>>(r_, wd, k_, a_, vl, s_, v0, misc_kkk, misc_a, yT);

    // groupnorm + bonus + gate -> z fp16
    post_kernel<<<(BT*HH)/8, 256>>>(yT, r_, k_, a_, vl, s_, v0, g_, faaaa,
                                    misc_a, ln_w, ln_b, z_);

    // output projection directly into d_out
    hgemm<0><<<dim3(CC/128, BT/128), 256, HSMEM>>>(
        z_, WoT, (float*)d_out, CC, CC, CC, nullptr);
}